// round 1
// baseline (speedup 1.0000x reference)
#include <cuda_runtime.h>

// Until operator, exact backward recurrence parallelized as a (max,min)-semiring scan.
// Shapes: phi, psi, out: [B=1024, T=8192, C=2] float32.
// Recurrence per (b, c): r[t] = max(min(1, psi[t]), min(phi[t], r[t+1])), r[T] = -inf.
//
// Element op: f_t(r) = max(v_t, min(p_t, r)) with v_t = min(1, psi[t]), p_t = phi[t].
// Composition (f applied AFTER g, i.e. earlier in time):
//   P = min(Pf, Pg);  V = max(Vf, min(Pf, Vg))
// Applying a composed op to -inf yields just V.

#define T_LEN 8192
#define BLK   512
#define STEPS 16              // T_LEN / BLK timesteps per thread
#define NF    (STEPS / 2)     // float4 chunks per thread (each float4 = 2 timesteps x 2 ch)
#define NW    (BLK / 32)      // warps per block

__device__ __forceinline__ float finf()  { return __int_as_float(0x7f800000); }
__device__ __forceinline__ float fninf() { return __int_as_float(0xff800000); }

__global__ void __launch_bounds__(BLK, 1)
until_kernel(const float4* __restrict__ phi,
             const float4* __restrict__ psi,
             float4* __restrict__ out)
{
    const int    b    = blockIdx.x;
    const size_t base = (size_t)b * (T_LEN / 2);   // row offset in float4 units
    const int    tid  = threadIdx.x;
    const int    lane = tid & 31;
    const int    w    = tid >> 5;
    const int    f0   = tid * NF;                  // this thread's first float4 index in row

    // ---- Load chunk into registers (phi raw, psi pre-clamped to v = min(1, psi)) ----
    float4 p[NF], v[NF];
#pragma unroll
    for (int i = 0; i < NF; i++) {
        p[i] = phi[base + f0 + i];
        float4 q = psi[base + f0 + i];
        v[i].x = fminf(1.0f, q.x);
        v[i].y = fminf(1.0f, q.y);
        v[i].z = fminf(1.0f, q.z);
        v[i].w = fminf(1.0f, q.w);
    }
    // float4 layout: .x = ch0@t, .y = ch1@t, .z = ch0@t+1, .w = ch1@t+1

    // ---- Per-thread composed op over its 16 timesteps (fold back-to-front) ----
    float Px = finf(), Vx = fninf();   // channel 0
    float Py = finf(), Vy = fninf();   // channel 1
#pragma unroll
    for (int i = NF - 1; i >= 0; i--) {
        // later timestep (.z/.w) first, then earlier (.x/.y)
        Vx = fmaxf(v[i].z, fminf(p[i].z, Vx)); Px = fminf(p[i].z, Px);
        Vy = fmaxf(v[i].w, fminf(p[i].w, Vy)); Py = fminf(p[i].w, Py);
        Vx = fmaxf(v[i].x, fminf(p[i].x, Vx)); Px = fminf(p[i].x, Px);
        Vy = fmaxf(v[i].y, fminf(p[i].y, Vy)); Py = fminf(p[i].y, Py);
    }

    // ---- Warp-level reverse inclusive scan (Kogge-Stone) of composed ops ----
#pragma unroll
    for (int off = 1; off < 32; off <<= 1) {
        float Px2 = __shfl_down_sync(0xffffffffu, Px, off);
        float Vx2 = __shfl_down_sync(0xffffffffu, Vx, off);
        float Py2 = __shfl_down_sync(0xffffffffu, Py, off);
        float Vy2 = __shfl_down_sync(0xffffffffu, Vy, off);
        if (lane + off < 32) {
            Vx = fmaxf(Vx, fminf(Px, Vx2)); Px = fminf(Px, Px2);
            Vy = fmaxf(Vy, fminf(Py, Vy2)); Py = fminf(Py, Py2);
        }
    }
    // (Px,Vx) now = inclusive suffix composition lane..31 within this warp.

    // Exclusive (suffix starting at lane+1); lane 31 gets identity.
    float EPx = __shfl_down_sync(0xffffffffu, Px, 1);
    float EVx = __shfl_down_sync(0xffffffffu, Vx, 1);
    float EPy = __shfl_down_sync(0xffffffffu, Py, 1);
    float EVy = __shfl_down_sync(0xffffffffu, Vy, 1);
    if (lane == 31) { EPx = finf(); EVx = fninf(); EPy = finf(); EVy = fninf(); }

    // ---- Cross-warp carry: warp totals in shared, each thread folds suffix warps ----
    __shared__ float4 wop[NW];     // (Px, Vx, Py, Vy) per warp
    if (lane == 0) wop[w] = make_float4(Px, Vx, Py, Vy);
    __syncthreads();

    float Ax = fninf(), Ay = fninf();   // value of r entering this warp from the right
    for (int j = NW - 1; j > w; j--) {
        float4 o = wop[j];
        Ax = fmaxf(o.y, fminf(o.x, Ax));
        Ay = fmaxf(o.w, fminf(o.z, Ay));
    }

    // carry entering this thread = exclusive-within-warp op applied to warp carry
    float rx = fmaxf(EVx, fminf(EPx, Ax));
    float ry = fmaxf(EVy, fminf(EPy, Ay));

    // ---- Backward sweep over the register-resident chunk; vectorized stores ----
#pragma unroll
    for (int i = NF - 1; i >= 0; i--) {
        rx = fmaxf(v[i].z, fminf(p[i].z, rx));
        ry = fmaxf(v[i].w, fminf(p[i].w, ry));
        float oz = rx, ow = ry;
        rx = fmaxf(v[i].x, fminf(p[i].x, rx));
        ry = fmaxf(v[i].y, fminf(p[i].y, ry));
        out[base + f0 + i] = make_float4(rx, ry, oz, ow);
    }
}

extern "C" void kernel_launch(void* const* d_in, const int* in_sizes, int n_in,
                              void* d_out, int out_size)
{
    const float4* phi = (const float4*)d_in[0];
    const float4* psi = (const float4*)d_in[1];
    float4*       o   = (float4*)d_out;
    // B = 1024 rows; one block per row
    until_kernel<<<1024, BLK>>>(phi, psi, o);
}

// round 2
// speedup vs baseline: 1.2698x; 1.2698x over previous
#include <cuda_runtime.h>

// Until operator, exact backward recurrence parallelized as a (max,min)-semiring scan.
// Shapes: phi, psi, out: [B=1024, T=8192, C=2] float32.
// r[t] = max(min(1, psi[t]), min(phi[t], r[t+1])), r[T] = -inf.
//
// Op f_t(r) = max(v_t, min(p_t, r)), v_t = min(1, psi[t]).
// Composition (f earlier in time than g): P = min(Pf,Pg); V = max(Vf, min(Pf,Vg)).
//
// R2: BLK 512->1024, STEPS 16->8. Payload regs halved (64->32) so a full
// 1024-thread block fits one SM at ~55 regs -> 32 warps resident (50% occ),
// doubling memory-level parallelism vs R1 (21.8% occ, DRAM 35%).

#define T_LEN 8192
#define BLK   1024
#define STEPS 8               // T_LEN / BLK timesteps per thread
#define NF    (STEPS / 2)     // float4 chunks per thread (2 timesteps x 2 ch each)
#define NW    (BLK / 32)      // warps per block

__device__ __forceinline__ float finf()  { return __int_as_float(0x7f800000); }
__device__ __forceinline__ float fninf() { return __int_as_float(0xff800000); }

__global__ void __launch_bounds__(BLK, 1)
until_kernel(const float4* __restrict__ phi,
             const float4* __restrict__ psi,
             float4* __restrict__ out)
{
    const int    b    = blockIdx.x;
    const size_t base = (size_t)b * (T_LEN / 2);   // row offset in float4 units
    const int    tid  = threadIdx.x;
    const int    lane = tid & 31;
    const int    w    = tid >> 5;
    const int    f0   = tid * NF;

    // ---- Load chunk (phi raw; psi pre-clamped to v = min(1, psi)) ----
    float4 p[NF], v[NF];
#pragma unroll
    for (int i = 0; i < NF; i++) {
        p[i] = phi[base + f0 + i];
        float4 q = psi[base + f0 + i];
        v[i].x = fminf(1.0f, q.x);
        v[i].y = fminf(1.0f, q.y);
        v[i].z = fminf(1.0f, q.z);
        v[i].w = fminf(1.0f, q.w);
    }
    // float4 layout: .x = ch0@t, .y = ch1@t, .z = ch0@t+1, .w = ch1@t+1

    // ---- Per-thread composed op (fold back-to-front) ----
    float Px = finf(), Vx = fninf();   // channel 0
    float Py = finf(), Vy = fninf();   // channel 1
#pragma unroll
    for (int i = NF - 1; i >= 0; i--) {
        Vx = fmaxf(v[i].z, fminf(p[i].z, Vx)); Px = fminf(p[i].z, Px);
        Vy = fmaxf(v[i].w, fminf(p[i].w, Vy)); Py = fminf(p[i].w, Py);
        Vx = fmaxf(v[i].x, fminf(p[i].x, Vx)); Px = fminf(p[i].x, Px);
        Vy = fmaxf(v[i].y, fminf(p[i].y, Vy)); Py = fminf(p[i].y, Py);
    }

    // ---- Warp-level reverse inclusive scan (Kogge-Stone) ----
#pragma unroll
    for (int off = 1; off < 32; off <<= 1) {
        float Px2 = __shfl_down_sync(0xffffffffu, Px, off);
        float Vx2 = __shfl_down_sync(0xffffffffu, Vx, off);
        float Py2 = __shfl_down_sync(0xffffffffu, Py, off);
        float Vy2 = __shfl_down_sync(0xffffffffu, Vy, off);
        if (lane + off < 32) {
            Vx = fmaxf(Vx, fminf(Px, Vx2)); Px = fminf(Px, Px2);
            Vy = fmaxf(Vy, fminf(Py, Vy2)); Py = fminf(Py, Py2);
        }
    }

    // Exclusive within warp (suffix starting at lane+1); lane 31 = identity.
    float EPx = __shfl_down_sync(0xffffffffu, Px, 1);
    float EVx = __shfl_down_sync(0xffffffffu, Vx, 1);
    float EPy = __shfl_down_sync(0xffffffffu, Py, 1);
    float EVy = __shfl_down_sync(0xffffffffu, Vy, 1);
    if (lane == 31) { EPx = finf(); EVx = fninf(); EPy = finf(); EVy = fninf(); }

    // ---- Cross-warp carry via shared warp totals ----
    __shared__ float4 wop[NW];     // (Px, Vx, Py, Vy) per warp
    if (lane == 0) wop[w] = make_float4(Px, Vx, Py, Vy);
    __syncthreads();

    float Ax = fninf(), Ay = fninf();   // r entering this warp from the right
    for (int j = NW - 1; j > w; j--) {
        float4 o = wop[j];
        Ax = fmaxf(o.y, fminf(o.x, Ax));
        Ay = fmaxf(o.w, fminf(o.z, Ay));
    }

    // carry entering this thread
    float rx = fmaxf(EVx, fminf(EPx, Ax));
    float ry = fmaxf(EVy, fminf(EPy, Ay));

    // ---- Backward sweep over register chunk; vectorized stores ----
#pragma unroll
    for (int i = NF - 1; i >= 0; i--) {
        rx = fmaxf(v[i].z, fminf(p[i].z, rx));
        ry = fmaxf(v[i].w, fminf(p[i].w, ry));
        float oz = rx, ow = ry;
        rx = fmaxf(v[i].x, fminf(p[i].x, rx));
        ry = fmaxf(v[i].y, fminf(p[i].y, ry));
        out[base + f0 + i] = make_float4(rx, ry, oz, ow);
    }
}

extern "C" void kernel_launch(void* const* d_in, const int* in_sizes, int n_in,
                              void* d_out, int out_size)
{
    const float4* phi = (const float4*)d_in[0];
    const float4* psi = (const float4*)d_in[1];
    float4*       o   = (float4*)d_out;
    until_kernel<<<1024, BLK>>>(phi, psi, o);
}